// round 1
// baseline (speedup 1.0000x reference)
#include <cuda_runtime.h>
#include <math.h>

#define N_RAYS 8192
#define NS 128
#define DIM0 66
#define HID 128

// Shared layout (floats):
//  w1s : 128*128 = 16384
//  h0s : 128*129 = 16512   (also reused as scan scratch before MLP)
//  h1s : 128*129 = 16512
//  b0s : 128
//  b1s : 128
//  ass : 128   (act_shift)
#define SMEM_FLOATS (16384 + 16512 + 16512 + 128 + 128 + 128)

__global__ void __launch_bounds__(128) mpi_render_kernel(
    const float* __restrict__ rays_o, const float* __restrict__ rays_d,
    const float* __restrict__ dens,   const float* __restrict__ k0g,
    const float* __restrict__ act_shift,
    const float* __restrict__ w0, const float* __restrict__ b0,
    const float* __restrict__ w1, const float* __restrict__ b1,
    const float* __restrict__ w2, const float* __restrict__ b2,
    float* __restrict__ out)
{
    extern __shared__ float sm[];
    float* w1s = sm;
    float* h0s = sm + 16384;
    float* h1s = h0s + 16512;
    float* b0s = h1s + 16512;
    float* b1s = b0s + 128;
    float* ass = b1s + 128;
    __shared__ float wprod[4];
    __shared__ float redbuf[12];

    const int ray  = blockIdx.x;
    const int s    = threadIdx.x;
    const int lane = s & 31;
    const int wid  = s >> 5;

    // ---- cooperative loads into shared ----
    #pragma unroll
    for (int i = 0; i < 128; i++) w1s[i * 128 + s] = w1[i * 128 + s];
    b0s[s] = b0[s];
    b1s[s] = b1[s];
    ass[s] = act_shift[s];

    // ---- per-sample point ----
    const float ox = rays_o[ray*3+0], oy = rays_o[ray*3+1], oz = rays_o[ray*3+2];
    const float dx = rays_d[ray*3+0], dy = rays_d[ray*3+1], dz = rays_d[ray*3+2];
    const float t  = (float)s * (1.0f / 127.0f);
    const float px = ox + dx * t;
    const float py = oy + dy * t;
    const float pz = oz + dz * t;

    __syncthreads();  // ass/w1s/b's ready

    // ---- grid coords (shared by density, k0, act_shift z-lerp) ----
    float ux = fminf(fmaxf((px + 1.0f) * 0.5f * 255.0f, 0.0f), 255.0f);
    float uy = fminf(fmaxf((py + 1.0f) * 0.5f * 255.0f, 0.0f), 255.0f);
    float uz = fminf(fmaxf(pz * 127.0f, 0.0f), 127.0f);
    int x0 = min((int)floorf(ux), 254);
    int y0 = min((int)floorf(uy), 254);
    int z0 = min((int)floorf(uz), 126);
    float fx = ux - (float)x0;
    float fy = uy - (float)y0;
    float fz = uz - (float)z0;
    const int base = (x0 * 256 + y0) * 128 + z0;  // strides: x:32768 y:128 z:1

    // ---- density trilerp ----
    float c000 = __ldg(dens + base);
    float c001 = __ldg(dens + base + 1);
    float c010 = __ldg(dens + base + 128);
    float c011 = __ldg(dens + base + 129);
    float c100 = __ldg(dens + base + 32768);
    float c101 = __ldg(dens + base + 32769);
    float c110 = __ldg(dens + base + 32896);
    float c111 = __ldg(dens + base + 32897);
    float gx = 1.0f - fx, gy = 1.0f - fy, gz = 1.0f - fz;
    float density =
        gx*gy*gz*c000 + gx*gy*fz*c001 + gx*fy*gz*c010 + gx*fy*fz*c011 +
        fx*gy*gz*c100 + fx*gy*fz*c101 + fx*fy*gz*c110 + fx*fy*fz*c111;

    // ---- act_shift 1D lerp (same z mapping as trilerp) ----
    float shift = ass[z0] + fz * (ass[z0 + 1] - ass[z0]);

    // ---- alpha ----
    float xv = density + shift;
    float sp = fmaxf(xv, 0.0f) + log1pf(expf(-fabsf(xv)));  // softplus
    float alpha = 1.0f - expf(-sp * 2.0f);                  // INTERVAL = 2
    float oma = 1.0f - alpha;

    // ---- cumprod scan for transmittance ----
    float p = oma;
    #pragma unroll
    for (int off = 1; off < 32; off <<= 1) {
        float n = __shfl_up_sync(0xffffffffu, p, off);
        if (lane >= off) p *= n;
    }
    if (lane == 31) wprod[wid] = p;
    __syncthreads();
    float pref = 1.0f;
    #pragma unroll
    for (int w = 0; w < 4; w++) if (w < wid) pref *= wprod[w];
    float trans = pref * p;
    h0s[s] = trans;   // scratch use before MLP
    __syncthreads();
    float t_prev = (s == 0) ? 1.0f : h0s[s - 1];
    float weight = alpha * t_prev;
    float alast  = h0s[127];
    __syncthreads();  // done with scratch before layer-0 writes

    // ---- k0 trilerp (12 channels) ----
    float k0v[12];
    #pragma unroll
    for (int i = 0; i < 12; i++) k0v[i] = 0.0f;
    #pragma unroll
    for (int dxi = 0; dxi < 2; dxi++) {
        float wx = dxi ? fx : gx;
        #pragma unroll
        for (int dyi = 0; dyi < 2; dyi++) {
            float wxy = wx * (dyi ? fy : gy);
            #pragma unroll
            for (int dzi = 0; dzi < 2; dzi++) {
                float w = wxy * (dzi ? fz : gz);
                const float4* q = (const float4*)(k0g +
                    (long long)(base + dxi * 32768 + dyi * 128 + dzi) * 12);
                float4 a = __ldg(q);
                float4 b = __ldg(q + 1);
                float4 c = __ldg(q + 2);
                k0v[0] += w*a.x; k0v[1] += w*a.y; k0v[2]  += w*a.z; k0v[3]  += w*a.w;
                k0v[4] += w*b.x; k0v[5] += w*b.y; k0v[6]  += w*b.z; k0v[7]  += w*b.w;
                k0v[8] += w*c.x; k0v[9] += w*c.y; k0v[10] += w*c.z; k0v[11] += w*c.w;
            }
        }
    }

    // ---- feature vector (66) ----
    float feat[DIM0];
    #pragma unroll
    for (int i = 0; i < 12; i++) feat[i] = k0v[i];
    {
        float P[3] = {px, py, pz};
        #pragma unroll
        for (int i = 0; i < 3; i++) {
            feat[12 + i] = P[i];
            #pragma unroll
            for (int f = 0; f < 4; f++) {
                float a = P[i] * (float)(1 << f);
                feat[15 + i * 4 + f] = sinf(a);
                feat[27 + i * 4 + f] = cosf(a);
            }
        }
        float inv = rsqrtf(dx*dx + dy*dy + dz*dz);
        float V[3] = {dx * inv, dy * inv, dz * inv};
        #pragma unroll
        for (int i = 0; i < 3; i++) {
            feat[39 + i] = V[i];
            #pragma unroll
            for (int f = 0; f < 4; f++) {
                float a = V[i] * (float)(1 << f);
                feat[42 + i * 4 + f] = sinf(a);
                feat[54 + i * 4 + f] = cosf(a);
            }
        }
    }

    const int row = s * 129;

    // ---- layer 0: 66 -> 128, weights from global (broadcast, L1-hot) ----
    #pragma unroll 1
    for (int j0 = 0; j0 < 128; j0 += 8) {
        float acc[8];
        #pragma unroll
        for (int jj = 0; jj < 8; jj++) acc[jj] = b0s[j0 + jj];
        #pragma unroll
        for (int k = 0; k < DIM0; k++) {
            float fk = feat[k];
            float4 wa = __ldg((const float4*)(w0 + k * 128 + j0));
            float4 wb = __ldg((const float4*)(w0 + k * 128 + j0 + 4));
            acc[0] += fk * wa.x; acc[1] += fk * wa.y;
            acc[2] += fk * wa.z; acc[3] += fk * wa.w;
            acc[4] += fk * wb.x; acc[5] += fk * wb.y;
            acc[6] += fk * wb.z; acc[7] += fk * wb.w;
        }
        #pragma unroll
        for (int jj = 0; jj < 8; jj++) h0s[row + j0 + jj] = fmaxf(acc[jj], 0.0f);
    }

    // ---- layer 1: 128 -> 128, weights from shared ----
    #pragma unroll 1
    for (int j0 = 0; j0 < 128; j0 += 8) {
        float acc[8];
        #pragma unroll
        for (int jj = 0; jj < 8; jj++) acc[jj] = b1s[j0 + jj];
        #pragma unroll 8
        for (int k = 0; k < HID; k++) {
            float hk = h0s[row + k];
            float4 wa = *(const float4*)(w1s + k * 128 + j0);
            float4 wb = *(const float4*)(w1s + k * 128 + j0 + 4);
            acc[0] += hk * wa.x; acc[1] += hk * wa.y;
            acc[2] += hk * wa.z; acc[3] += hk * wa.w;
            acc[4] += hk * wb.x; acc[5] += hk * wb.y;
            acc[6] += hk * wb.z; acc[7] += hk * wb.w;
        }
        #pragma unroll
        for (int jj = 0; jj < 8; jj++) h1s[row + j0 + jj] = fmaxf(acc[jj], 0.0f);
    }

    // ---- layer 2: 128 -> 3 + sigmoid ----
    float a0 = __ldg(b2 + 0), a1 = __ldg(b2 + 1), a2 = __ldg(b2 + 2);
    #pragma unroll 8
    for (int k = 0; k < HID; k++) {
        float hk = h1s[row + k];
        a0 += hk * __ldg(w2 + k * 3 + 0);
        a1 += hk * __ldg(w2 + k * 3 + 1);
        a2 += hk * __ldg(w2 + k * 3 + 2);
    }
    float r0 = weight / (1.0f + expf(-a0));
    float r1 = weight / (1.0f + expf(-a1));
    float r2 = weight / (1.0f + expf(-a2));

    // ---- reduce over samples ----
    #pragma unroll
    for (int off = 16; off; off >>= 1) {
        r0 += __shfl_down_sync(0xffffffffu, r0, off);
        r1 += __shfl_down_sync(0xffffffffu, r1, off);
        r2 += __shfl_down_sync(0xffffffffu, r2, off);
    }
    if (lane == 0) {
        redbuf[wid * 3 + 0] = r0;
        redbuf[wid * 3 + 1] = r1;
        redbuf[wid * 3 + 2] = r2;
    }
    __syncthreads();
    if (s == 0) {
        float o0 = alast, o1 = alast, o2 = alast;  // BG = 1.0
        #pragma unroll
        for (int w = 0; w < 4; w++) {
            o0 += redbuf[w * 3 + 0];
            o1 += redbuf[w * 3 + 1];
            o2 += redbuf[w * 3 + 2];
        }
        out[ray * 3 + 0] = o0;
        out[ray * 3 + 1] = o1;
        out[ray * 3 + 2] = o2;
    }
}

extern "C" void kernel_launch(void* const* d_in, const int* in_sizes, int n_in,
                              void* d_out, int out_size)
{
    const float* rays_o    = (const float*)d_in[0];
    const float* rays_d    = (const float*)d_in[1];
    const float* dens      = (const float*)d_in[2];
    const float* k0g       = (const float*)d_in[3];
    const float* act_shift = (const float*)d_in[4];
    const float* w0        = (const float*)d_in[5];
    const float* b0        = (const float*)d_in[6];
    const float* w1        = (const float*)d_in[7];
    const float* b1        = (const float*)d_in[8];
    const float* w2        = (const float*)d_in[9];
    const float* b2        = (const float*)d_in[10];
    float* out = (float*)d_out;

    size_t smem = SMEM_FLOATS * sizeof(float);  // ~195 KB
    cudaFuncSetAttribute(mpi_render_kernel,
                         cudaFuncAttributeMaxDynamicSharedMemorySize, (int)smem);
    mpi_render_kernel<<<N_RAYS, 128, smem>>>(
        rays_o, rays_d, dens, k0g, act_shift,
        w0, b0, w1, b1, w2, b2, out);
}

// round 2
// speedup vs baseline: 3.3806x; 3.3806x over previous
#include <cuda_runtime.h>
#include <math.h>

#define N_RAYS 8192

typedef unsigned long long ull;

__device__ __forceinline__ ull pk2(float x) {
    ull r; asm("mov.b64 %0, {%1, %1};" : "=l"(r) : "f"(x)); return r;
}
__device__ __forceinline__ void fma2(ull& d, ull a, ull b) {
    asm("fma.rn.f32x2 %0, %1, %2, %0;" : "+l"(d) : "l"(a), "l"(b));
}
__device__ __forceinline__ float2 up2(ull p) {
    float2 r; asm("mov.b64 {%0, %1}, %2;" : "=f"(r.x), "=f"(r.y) : "l"(p)); return r;
}

// Shared layout (float offsets)
#define W1S_OFF 0                       // 128*128 = 16384
#define W0S_OFF 16384                   // 39*128  = 4992
#define H0S_OFF (16384 + 4992)          // 256*129 = 33024
#define W2P_OFF (H0S_OFF + 33024)       // 128*4   = 512
#define VB_OFF  (W2P_OFF + 512)         // 256 (also scan scratch)
#define B1S_OFF (VB_OFF + 256)          // 128
#define ASS_OFF (B1S_OFF + 128)         // 128
#define SMEM_FLOATS (ASS_OFF + 128)     // 55424 floats = 221696 B

__global__ void __launch_bounds__(256, 1) mpi_render_kernel(
    const float* __restrict__ rays_o, const float* __restrict__ rays_d,
    const float* __restrict__ dens,   const float* __restrict__ k0g,
    const float* __restrict__ act_shift,
    const float* __restrict__ w0, const float* __restrict__ b0,
    const float* __restrict__ w1, const float* __restrict__ b1,
    const float* __restrict__ w2, const float* __restrict__ b2,
    float* __restrict__ out)
{
    extern __shared__ float sm[];
    __shared__ float wprod[8];
    __shared__ float redbuf[24];

    const int tid     = threadIdx.x;
    const int lane    = tid & 31;
    const int wid     = tid >> 5;        // 0..7
    const int rayslot = tid >> 7;        // 0,1
    const int s       = tid & 127;       // sample within ray
    const int ray     = blockIdx.x * 2 + rayslot;
    const int jcol    = tid & 127;

    // ---- stage weights into shared (coalesced) ----
    {
        const float4* w1g = (const float4*)w1;
        float4* w1sv = (float4*)(sm + W1S_OFF);
        #pragma unroll 4
        for (int i = tid; i < 4096; i += 256) w1sv[i] = w1g[i];
        const float4* w0g = (const float4*)w0;     // rows 0..38 = first 1248 float4
        float4* w0sv = (float4*)(sm + W0S_OFF);
        #pragma unroll 2
        for (int i = tid; i < 1248; i += 256) w0sv[i] = w0g[i];
        if (tid < 128) {
            sm[B1S_OFF + tid] = b1[tid];
            sm[ASS_OFF + tid] = act_shift[tid];
            float* wp = sm + W2P_OFF + tid * 4;
            wp[0] = w2[tid * 3 + 0];
            wp[1] = w2[tid * 3 + 1];
            wp[2] = w2[tid * 3 + 2];
            wp[3] = 0.0f;
        }
    }

    // ---- per-sample point ----
    const float ox = rays_o[ray*3+0], oy = rays_o[ray*3+1], oz = rays_o[ray*3+2];
    const float dx = rays_d[ray*3+0], dy = rays_d[ray*3+1], dz = rays_d[ray*3+2];
    const float t  = (float)s * (1.0f / 127.0f);
    const float px = ox + dx * t;
    const float py = oy + dy * t;
    const float pz = oz + dz * t;

    // ---- grid coords ----
    float ux = fminf(fmaxf((px + 1.0f) * 0.5f * 255.0f, 0.0f), 255.0f);
    float uy = fminf(fmaxf((py + 1.0f) * 0.5f * 255.0f, 0.0f), 255.0f);
    float uz = fminf(fmaxf(pz * 127.0f, 0.0f), 127.0f);
    int x0 = min((int)floorf(ux), 254);
    int y0 = min((int)floorf(uy), 254);
    int z0 = min((int)floorf(uz), 126);
    float fx = ux - (float)x0;
    float fy = uy - (float)y0;
    float fz = uz - (float)z0;
    const int base = (x0 * 256 + y0) * 128 + z0;

    // ---- density trilerp ----
    float c000 = __ldg(dens + base);
    float c001 = __ldg(dens + base + 1);
    float c010 = __ldg(dens + base + 128);
    float c011 = __ldg(dens + base + 129);
    float c100 = __ldg(dens + base + 32768);
    float c101 = __ldg(dens + base + 32769);
    float c110 = __ldg(dens + base + 32896);
    float c111 = __ldg(dens + base + 32897);
    float gx = 1.0f - fx, gy = 1.0f - fy, gz = 1.0f - fz;
    float density =
        gx*gy*gz*c000 + gx*gy*fz*c001 + gx*fy*gz*c010 + gx*fy*fz*c011 +
        fx*gy*gz*c100 + fx*gy*fz*c101 + fx*fy*gz*c110 + fx*fy*fz*c111;

    __syncthreads();  // staging visible (ass needed next)

    // ---- act_shift lerp + alpha ----
    float shift = sm[ASS_OFF + z0] + fz * (sm[ASS_OFF + z0 + 1] - sm[ASS_OFF + z0]);
    float xv = density + shift;
    float sp = fmaxf(xv, 0.0f) + log1pf(__expf(-fabsf(xv)));
    float alpha = 1.0f - __expf(-sp * 2.0f);
    float oma = 1.0f - alpha;

    // ---- cumprod scan (per-ray over 128 threads = 4 warps) ----
    float p = oma;
    #pragma unroll
    for (int off = 1; off < 32; off <<= 1) {
        float n = __shfl_up_sync(0xffffffffu, p, off);
        if (lane >= off) p *= n;
    }
    if (lane == 31) wprod[wid] = p;
    __syncthreads();
    float pref = 1.0f;
    const int wb = rayslot * 4;
    #pragma unroll
    for (int w = 0; w < 4; w++) if (wb + w < wid) pref *= wprod[wb + w];
    float trans = pref * p;
    sm[VB_OFF + tid] = trans;          // scan scratch (vb region, pre-vbias)
    __syncthreads();
    float t_prev = (s == 0) ? 1.0f : sm[VB_OFF + tid - 1];
    float alast  = sm[VB_OFF + rayslot * 128 + 127];
    float weight = alpha * t_prev;
    __syncthreads();  // scratch reads done before vb overwrite

    // ---- k0 trilerp (12 ch) ----
    float k0v[12];
    #pragma unroll
    for (int i = 0; i < 12; i++) k0v[i] = 0.0f;
    #pragma unroll
    for (int dxi = 0; dxi < 2; dxi++) {
        float wx = dxi ? fx : gx;
        #pragma unroll
        for (int dyi = 0; dyi < 2; dyi++) {
            float wxy = wx * (dyi ? fy : gy);
            #pragma unroll
            for (int dzi = 0; dzi < 2; dzi++) {
                float w = wxy * (dzi ? fz : gz);
                const float4* q = (const float4*)(k0g +
                    (long long)(base + dxi * 32768 + dyi * 128 + dzi) * 12);
                float4 a = __ldg(q);
                float4 b = __ldg(q + 1);
                float4 c = __ldg(q + 2);
                k0v[0] += w*a.x; k0v[1] += w*a.y; k0v[2]  += w*a.z; k0v[3]  += w*a.w;
                k0v[4] += w*b.x; k0v[5] += w*b.y; k0v[6]  += w*b.z; k0v[7]  += w*b.w;
                k0v[8] += w*c.x; k0v[9] += w*c.y; k0v[10] += w*c.z; k0v[11] += w*c.w;
            }
        }
    }

    // ---- view-embedding fold: vb[j] = b0[j] + vemb . w0[39:66, j] ----
    {
        float inv = rsqrtf(dx*dx + dy*dy + dz*dz);
        float V[3] = {dx * inv, dy * inv, dz * inv};
        float ve[27];
        #pragma unroll
        for (int i = 0; i < 3; i++) {
            ve[i] = V[i];
            #pragma unroll
            for (int f = 0; f < 4; f++) {
                __sincosf(V[i] * (float)(1 << f), &ve[3 + i*4 + f], &ve[15 + i*4 + f]);
            }
        }
        float acc = __ldg(b0 + jcol);
        #pragma unroll
        for (int k = 0; k < 27; k++)
            acc += ve[k] * __ldg(w0 + (39 + k) * 128 + jcol);
        sm[VB_OFF + tid] = acc;
    }

    // ---- per-sample feature vector (39) ----
    float feat[39];
    #pragma unroll
    for (int i = 0; i < 12; i++) feat[i] = k0v[i];
    {
        float P[3] = {px, py, pz};
        #pragma unroll
        for (int i = 0; i < 3; i++) {
            feat[12 + i] = P[i];
            #pragma unroll
            for (int f = 0; f < 4; f++) {
                __sincosf(P[i] * (float)(1 << f), &feat[15 + i*4 + f], &feat[27 + i*4 + f]);
            }
        }
    }

    __syncthreads();  // vb + all staging ready

    // ---- layer 0: 39 -> 128 (f32x2), h0 -> private shared row ----
    const int srow = tid * 129;
    {
        const float* w0s_ = sm + W0S_OFF;
        #pragma unroll 1
        for (int j0 = 0; j0 < 128; j0 += 16) {
            ull A[8];
            const ulonglong2* vbp = (const ulonglong2*)(sm + VB_OFF + rayslot * 128 + j0);
            ulonglong2 v0 = vbp[0], v1 = vbp[1], v2 = vbp[2], v3 = vbp[3];
            A[0]=v0.x; A[1]=v0.y; A[2]=v1.x; A[3]=v1.y;
            A[4]=v2.x; A[5]=v2.y; A[6]=v3.x; A[7]=v3.y;
            #pragma unroll
            for (int k = 0; k < 39; k++) {
                ull fk = pk2(feat[k]);
                const ulonglong2* wp = (const ulonglong2*)(w0s_ + k * 128 + j0);
                ulonglong2 wa = wp[0], wc = wp[1];
                fma2(A[0], fk, wa.x); fma2(A[1], fk, wa.y);
                fma2(A[2], fk, wc.x); fma2(A[3], fk, wc.y);
                ulonglong2 we = wp[2], wg = wp[3];
                fma2(A[4], fk, we.x); fma2(A[5], fk, we.y);
                fma2(A[6], fk, wg.x); fma2(A[7], fk, wg.y);
            }
            float* hr = sm + H0S_OFF + srow + j0;
            #pragma unroll
            for (int i = 0; i < 8; i++) {
                float2 v = up2(A[i]);
                hr[2*i]     = fmaxf(v.x, 0.0f);
                hr[2*i + 1] = fmaxf(v.y, 0.0f);
            }
        }
    }

    // ---- layer 1 (128->128, f32x2) fused with layer 2 (128->3) ----
    float a0 = __ldg(b2 + 0), a1 = __ldg(b2 + 1), a2 = __ldg(b2 + 2);
    {
        const float* hrow = sm + H0S_OFF + srow;
        const float* w1s_ = sm + W1S_OFF;
        #pragma unroll 1
        for (int j0 = 0; j0 < 128; j0 += 16) {
            ull A[8];
            const ulonglong2* bp = (const ulonglong2*)(sm + B1S_OFF + j0);
            ulonglong2 v0 = bp[0], v1 = bp[1], v2 = bp[2], v3 = bp[3];
            A[0]=v0.x; A[1]=v0.y; A[2]=v1.x; A[3]=v1.y;
            A[4]=v2.x; A[5]=v2.y; A[6]=v3.x; A[7]=v3.y;
            #pragma unroll 8
            for (int k = 0; k < 128; k++) {
                ull hk = pk2(hrow[k]);
                const ulonglong2* wp = (const ulonglong2*)(w1s_ + k * 128 + j0);
                ulonglong2 wa = wp[0], wc = wp[1];
                fma2(A[0], hk, wa.x); fma2(A[1], hk, wa.y);
                fma2(A[2], hk, wc.x); fma2(A[3], hk, wc.y);
                ulonglong2 we = wp[2], wg = wp[3];
                fma2(A[4], hk, we.x); fma2(A[5], hk, we.y);
                fma2(A[6], hk, wg.x); fma2(A[7], hk, wg.y);
            }
            // consume h1 chunk into RGB accumulators
            #pragma unroll
            for (int i = 0; i < 8; i++) {
                float2 v = up2(A[i]);
                float ha = fmaxf(v.x, 0.0f);
                float hb = fmaxf(v.y, 0.0f);
                const float4 wva = *(const float4*)(sm + W2P_OFF + (j0 + 2*i) * 4);
                const float4 wvb = *(const float4*)(sm + W2P_OFF + (j0 + 2*i + 1) * 4);
                a0 += ha * wva.x + hb * wvb.x;
                a1 += ha * wva.y + hb * wvb.y;
                a2 += ha * wva.z + hb * wvb.z;
            }
        }
    }

    // ---- sigmoid, weight, reduce ----
    float r0 = weight / (1.0f + __expf(-a0));
    float r1 = weight / (1.0f + __expf(-a1));
    float r2 = weight / (1.0f + __expf(-a2));
    #pragma unroll
    for (int off = 16; off; off >>= 1) {
        r0 += __shfl_down_sync(0xffffffffu, r0, off);
        r1 += __shfl_down_sync(0xffffffffu, r1, off);
        r2 += __shfl_down_sync(0xffffffffu, r2, off);
    }
    if (lane == 0) {
        redbuf[wid * 3 + 0] = r0;
        redbuf[wid * 3 + 1] = r1;
        redbuf[wid * 3 + 2] = r2;
    }
    __syncthreads();
    if (s == 0) {
        float o0 = alast, o1 = alast, o2 = alast;  // BG = 1.0
        #pragma unroll
        for (int w = 0; w < 4; w++) {
            o0 += redbuf[(wb + w) * 3 + 0];
            o1 += redbuf[(wb + w) * 3 + 1];
            o2 += redbuf[(wb + w) * 3 + 2];
        }
        out[ray * 3 + 0] = o0;
        out[ray * 3 + 1] = o1;
        out[ray * 3 + 2] = o2;
    }
}

extern "C" void kernel_launch(void* const* d_in, const int* in_sizes, int n_in,
                              void* d_out, int out_size)
{
    const float* rays_o    = (const float*)d_in[0];
    const float* rays_d    = (const float*)d_in[1];
    const float* dens      = (const float*)d_in[2];
    const float* k0g       = (const float*)d_in[3];
    const float* act_shift = (const float*)d_in[4];
    const float* w0        = (const float*)d_in[5];
    const float* b0        = (const float*)d_in[6];
    const float* w1        = (const float*)d_in[7];
    const float* b1        = (const float*)d_in[8];
    const float* w2        = (const float*)d_in[9];
    const float* b2        = (const float*)d_in[10];
    float* out = (float*)d_out;

    size_t smem = SMEM_FLOATS * sizeof(float);  // ~216.5 KB
    cudaFuncSetAttribute(mpi_render_kernel,
                         cudaFuncAttributeMaxDynamicSharedMemorySize, (int)smem);
    mpi_render_kernel<<<N_RAYS / 2, 256, smem>>>(
        rays_o, rays_d, dens, k0g, act_shift,
        w0, b0, w1, b1, w2, b2, out);
}

// round 3
// speedup vs baseline: 5.2634x; 1.5569x over previous
#include <cuda_runtime.h>
#include <math.h>

#define N_RAYS 8192
typedef unsigned long long ull;

__device__ __forceinline__ ull pk2(float x) {
    ull r; asm("mov.b64 %0, {%1, %1};" : "=l"(r) : "f"(x)); return r;
}
__device__ __forceinline__ void fma2(ull& d, ull a, ull b) {
    asm("fma.rn.f32x2 %0, %1, %2, %0;" : "+l"(d) : "l"(a), "l"(b));
}
__device__ __forceinline__ float2 up2(ull p) {
    float2 r; asm("mov.b64 {%0, %1}, %2;" : "=f"(r.x), "=f"(r.y) : "l"(p)); return r;
}

// Shared layout (float offsets)
#define W1S 0                       // 128*128 = 16384
#define W0S 16384                   // 39*128  = 4992
#define FT  (W0S + 4992)            // 39 rows x 264 = 10296
#define H0T (FT + 10296)            // 128 rows x 132 = 16896
#define VB  (H0T + 16896)           // 256
#define B1S (VB + 256)              // 128
#define ASS (B1S + 128)             // 128
#define W2P (ASS + 128)             // 128*4 = 512
#define WAR (W2P + 512)             // 256 (weights / scan scratch)
#define PARTB (WAR + 256)           // 512
#define SMEM_FLOATS (PARTB + 512)   // 49848 fl = 199392 B

__global__ void __launch_bounds__(256, 1) mpi_render_kernel(
    const float* __restrict__ rays_o, const float* __restrict__ rays_d,
    const float* __restrict__ dens,   const float* __restrict__ k0g,
    const float* __restrict__ act_shift,
    const float* __restrict__ w0, const float* __restrict__ b0,
    const float* __restrict__ w1, const float* __restrict__ b1,
    const float* __restrict__ w2, const float* __restrict__ b2,
    float* __restrict__ out)
{
    extern __shared__ float sm[];
    __shared__ float wprod[8];
    __shared__ float redbuf[12];
    __shared__ float alast2[2];

    const int tid     = threadIdx.x;
    const int lane    = tid & 31;
    const int wid     = tid >> 5;
    const int rayslot = tid >> 7;
    const int s       = tid & 127;

    // ======== stage weights ========
    {
        const float4* w1g = (const float4*)w1;
        float4* w1sv = (float4*)(sm + W1S);
        #pragma unroll 4
        for (int i = tid; i < 4096; i += 256) w1sv[i] = w1g[i];
        const float4* w0g = (const float4*)w0;   // rows 0..38
        float4* w0sv = (float4*)(sm + W0S);
        #pragma unroll 2
        for (int i = tid; i < 1248; i += 256) w0sv[i] = w0g[i];
        if (tid < 128) {
            sm[B1S + tid] = b1[tid];
            sm[ASS + tid] = act_shift[tid];
            float* wp = sm + W2P + tid * 4;
            wp[0] = w2[tid * 3 + 0];
            wp[1] = w2[tid * 3 + 1];
            wp[2] = w2[tid * 3 + 2];
            wp[3] = 0.0f;
        }
    }

    // ======== phase A: per-sample geometry ========
    const int ray = blockIdx.x * 2 + rayslot;
    const float ox = rays_o[ray*3+0], oy = rays_o[ray*3+1], oz = rays_o[ray*3+2];
    const float dx = rays_d[ray*3+0], dy = rays_d[ray*3+1], dz = rays_d[ray*3+2];
    const float t  = (float)s * (1.0f / 127.0f);
    const float px = ox + dx * t;
    const float py = oy + dy * t;
    const float pz = oz + dz * t;

    float ux = fminf(fmaxf((px + 1.0f) * 0.5f * 255.0f, 0.0f), 255.0f);
    float uy = fminf(fmaxf((py + 1.0f) * 0.5f * 255.0f, 0.0f), 255.0f);
    float uz = fminf(fmaxf(pz * 127.0f, 0.0f), 127.0f);
    int x0 = min((int)floorf(ux), 254);
    int y0 = min((int)floorf(uy), 254);
    int z0 = min((int)floorf(uz), 126);
    float fx = ux - (float)x0;
    float fy = uy - (float)y0;
    float fz = uz - (float)z0;
    const int base = (x0 * 256 + y0) * 128 + z0;

    float c000 = __ldg(dens + base);
    float c001 = __ldg(dens + base + 1);
    float c010 = __ldg(dens + base + 128);
    float c011 = __ldg(dens + base + 129);
    float c100 = __ldg(dens + base + 32768);
    float c101 = __ldg(dens + base + 32769);
    float c110 = __ldg(dens + base + 32896);
    float c111 = __ldg(dens + base + 32897);
    float gx = 1.0f - fx, gy = 1.0f - fy, gz = 1.0f - fz;
    float density =
        gx*gy*gz*c000 + gx*gy*fz*c001 + gx*fy*gz*c010 + gx*fy*fz*c011 +
        fx*gy*gz*c100 + fx*gy*fz*c101 + fx*fy*gz*c110 + fx*fy*fz*c111;

    __syncthreads();  // staging visible

    float shift = sm[ASS + z0] + fz * (sm[ASS + z0 + 1] - sm[ASS + z0]);
    float xv = density + shift;
    float sp = fmaxf(xv, 0.0f) + log1pf(__expf(-fabsf(xv)));
    float alpha = 1.0f - __expf(-sp * 2.0f);
    float oma = 1.0f - alpha;

    // cumprod scan (4 warps per ray)
    float p = oma;
    #pragma unroll
    for (int off = 1; off < 32; off <<= 1) {
        float n = __shfl_up_sync(0xffffffffu, p, off);
        if (lane >= off) p *= n;
    }
    if (lane == 31) wprod[wid] = p;
    __syncthreads();
    float pref = 1.0f;
    const int wb = rayslot * 4;
    #pragma unroll
    for (int w = 0; w < 4; w++) if (wb + w < wid) pref *= wprod[wb + w];
    float trans = pref * p;
    sm[WAR + tid] = trans;
    __syncthreads();
    float t_prev = (s == 0) ? 1.0f : sm[WAR + tid - 1];
    float weight = alpha * t_prev;
    if (s == 127) alast2[rayslot] = trans;
    __syncthreads();
    sm[WAR + tid] = weight;

    // k0 trilerp (12 ch)
    float k0v[12];
    #pragma unroll
    for (int i = 0; i < 12; i++) k0v[i] = 0.0f;
    #pragma unroll
    for (int dxi = 0; dxi < 2; dxi++) {
        float wx = dxi ? fx : gx;
        #pragma unroll
        for (int dyi = 0; dyi < 2; dyi++) {
            float wxy = wx * (dyi ? fy : gy);
            #pragma unroll
            for (int dzi = 0; dzi < 2; dzi++) {
                float wv = wxy * (dzi ? fz : gz);
                const float4* q = (const float4*)(k0g +
                    (long long)(base + dxi * 32768 + dyi * 128 + dzi) * 12);
                float4 a = __ldg(q);
                float4 b = __ldg(q + 1);
                float4 c = __ldg(q + 2);
                k0v[0] += wv*a.x; k0v[1] += wv*a.y; k0v[2]  += wv*a.z; k0v[3]  += wv*a.w;
                k0v[4] += wv*b.x; k0v[5] += wv*b.y; k0v[6]  += wv*b.z; k0v[7]  += wv*b.w;
                k0v[8] += wv*c.x; k0v[9] += wv*c.y; k0v[10] += wv*c.z; k0v[11] += wv*c.w;
            }
        }
    }

    // view-embedding fold: vb[tid] = b0[jcol] + vemb . w0[39:66, jcol]
    {
        const int jcol = tid & 127;
        float inv = rsqrtf(dx*dx + dy*dy + dz*dz);
        float V[3] = {dx * inv, dy * inv, dz * inv};
        float ve[27];
        #pragma unroll
        for (int i = 0; i < 3; i++) {
            ve[i] = V[i];
            #pragma unroll
            for (int f = 0; f < 4; f++) {
                __sincosf(V[i] * (float)(1 << f), &ve[3 + i*4 + f], &ve[15 + i*4 + f]);
            }
        }
        float acc = __ldg(b0 + jcol);
        #pragma unroll
        for (int k = 0; k < 27; k++)
            acc += ve[k] * __ldg(w0 + (39 + k) * 128 + jcol);
        sm[VB + tid] = acc;
    }

    // features -> FT transposed [k][sample]; sample column = tid
    {
        float feat[39];
        #pragma unroll
        for (int i = 0; i < 12; i++) feat[i] = k0v[i];
        float P[3] = {px, py, pz};
        #pragma unroll
        for (int i = 0; i < 3; i++) {
            feat[12 + i] = P[i];
            #pragma unroll
            for (int f = 0; f < 4; f++) {
                __sincosf(P[i] * (float)(1 << f), &feat[15 + i*4 + f], &feat[27 + i*4 + f]);
            }
        }
        #pragma unroll
        for (int k = 0; k < 39; k++) sm[FT + k * 264 + tid] = feat[k];
    }

    __syncthreads();  // FT, vb, weights ready

    // ======== GEMM phase ========
    // thread grid 16x16: tm = tid&15 (m dir), tn = tid>>4 (n dir)
    // thread's m-set: {4tm..4tm+3, 64+4tm..64+4tm+3}; n-set: 8tn..8tn+7
    const int tm = tid & 15, tn = tid >> 4;
    const int ma = 4 * tm;          // first m quad
    const int n0 = 8 * tn;

    for (int pass = 0; pass < 2; pass++) {
        // ---- GEMM0: h0 = relu(F * W0 + vb), M=128 K=39 N=128 ----
        ull A[8][4];
        {
            const ull* vbp = (const ull*)(sm + VB + pass * 128 + n0);
            ull v0 = vbp[0], v1 = vbp[1], v2 = vbp[2], v3 = vbp[3];
            #pragma unroll
            for (int mi = 0; mi < 8; mi++) {
                A[mi][0] = v0; A[mi][1] = v1; A[mi][2] = v2; A[mi][3] = v3;
            }
            const float* fta = sm + FT + pass * 128 + ma;
            const float* w0b = sm + W0S + n0;
            #pragma unroll 4
            for (int k = 0; k < 39; k++) {
                float4 a0 = *(const float4*)(fta + k * 264);
                float4 a1 = *(const float4*)(fta + k * 264 + 64);
                const ull* wp = (const ull*)(w0b + k * 128);
                ull b0_ = wp[0], b1_ = wp[1], b2_ = wp[2], b3_ = wp[3];
                float am[8] = {a0.x, a0.y, a0.z, a0.w, a1.x, a1.y, a1.z, a1.w};
                #pragma unroll
                for (int mi = 0; mi < 8; mi++) {
                    ull av = pk2(am[mi]);
                    fma2(A[mi][0], av, b0_); fma2(A[mi][1], av, b1_);
                    fma2(A[mi][2], av, b2_); fma2(A[mi][3], av, b3_);
                }
            }
        }
        if (pass == 1) __syncthreads();  // phase C of pass 0 done reading H0T
        // store relu(h0) -> H0T[n][m]
        #pragma unroll
        for (int nn = 0; nn < 8; nn++) {
            const int nj = nn >> 1;
            float q[8];
            #pragma unroll
            for (int mi = 0; mi < 8; mi++) {
                float2 v = up2(A[mi][nj]);
                q[mi] = fmaxf((nn & 1) ? v.y : v.x, 0.0f);
            }
            float* hr = sm + H0T + (n0 + nn) * 132;
            *(float4*)(hr + ma)      = make_float4(q[0], q[1], q[2], q[3]);
            *(float4*)(hr + 64 + ma) = make_float4(q[4], q[5], q[6], q[7]);
        }
        __syncthreads();

        // ---- GEMM1: h1 = relu(H0 * W1 + b1), K=128 ----
        {
            const ull* bp = (const ull*)(sm + B1S + n0);
            ull v0 = bp[0], v1 = bp[1], v2 = bp[2], v3 = bp[3];
            #pragma unroll
            for (int mi = 0; mi < 8; mi++) {
                A[mi][0] = v0; A[mi][1] = v1; A[mi][2] = v2; A[mi][3] = v3;
            }
            const float* h0a = sm + H0T + ma;
            const float* w1b = sm + W1S + n0;
            #pragma unroll 4
            for (int k = 0; k < 128; k++) {
                float4 a0 = *(const float4*)(h0a + k * 132);
                float4 a1 = *(const float4*)(h0a + k * 132 + 64);
                const ull* wp = (const ull*)(w1b + k * 128);
                ull b0_ = wp[0], b1_ = wp[1], b2_ = wp[2], b3_ = wp[3];
                float am[8] = {a0.x, a0.y, a0.z, a0.w, a1.x, a1.y, a1.z, a1.w};
                #pragma unroll
                for (int mi = 0; mi < 8; mi++) {
                    ull av = pk2(am[mi]);
                    fma2(A[mi][0], av, b0_); fma2(A[mi][1], av, b1_);
                    fma2(A[mi][2], av, b2_); fma2(A[mi][3], av, b3_);
                }
            }
        }
        __syncthreads();  // all H0T reads done
        // store relu(h1) -> H0T[j][m]
        #pragma unroll
        for (int nn = 0; nn < 8; nn++) {
            const int nj = nn >> 1;
            float q[8];
            #pragma unroll
            for (int mi = 0; mi < 8; mi++) {
                float2 v = up2(A[mi][nj]);
                q[mi] = fmaxf((nn & 1) ? v.y : v.x, 0.0f);
            }
            float* hr = sm + H0T + (n0 + nn) * 132;
            *(float4*)(hr + ma)      = make_float4(q[0], q[1], q[2], q[3]);
            *(float4*)(hr + 64 + ma) = make_float4(q[4], q[5], q[6], q[7]);
        }
        __syncthreads();

        // ---- phase C: layer 2 + sigmoid + weighted reduce ----
        {
            const int m  = tid & 127;
            const int jh = tid >> 7;
            float r0, r1, r2;
            if (jh == 0) { r0 = __ldg(b2+0); r1 = __ldg(b2+1); r2 = __ldg(b2+2); }
            else         { r0 = r1 = r2 = 0.0f; }
            const float* hb  = sm + H0T + jh * 64 * 132 + m;
            const float* w2b = sm + W2P + jh * 64 * 4;
            #pragma unroll 8
            for (int j = 0; j < 64; j++) {
                float h = hb[j * 132];
                const float4 wv = *(const float4*)(w2b + j * 4);
                r0 += h * wv.x; r1 += h * wv.y; r2 += h * wv.z;
            }
            if (jh == 1) {
                sm[PARTB + m*4 + 0] = r0;
                sm[PARTB + m*4 + 1] = r1;
                sm[PARTB + m*4 + 2] = r2;
            }
            __syncthreads();
            if (jh == 0) {
                r0 += sm[PARTB + m*4 + 0];
                r1 += sm[PARTB + m*4 + 1];
                r2 += sm[PARTB + m*4 + 2];
                float w = sm[WAR + pass * 128 + m];
                r0 = w / (1.0f + __expf(-r0));
                r1 = w / (1.0f + __expf(-r1));
                r2 = w / (1.0f + __expf(-r2));
                #pragma unroll
                for (int off = 16; off; off >>= 1) {
                    r0 += __shfl_down_sync(0xffffffffu, r0, off);
                    r1 += __shfl_down_sync(0xffffffffu, r1, off);
                    r2 += __shfl_down_sync(0xffffffffu, r2, off);
                }
                if (lane == 0) {
                    redbuf[wid * 3 + 0] = r0;
                    redbuf[wid * 3 + 1] = r1;
                    redbuf[wid * 3 + 2] = r2;
                }
            }
            __syncthreads();
            if (tid == 0) {
                float al = alast2[pass];
                float o0 = al, o1 = al, o2 = al;   // BG = 1
                #pragma unroll
                for (int w = 0; w < 4; w++) {
                    o0 += redbuf[w * 3 + 0];
                    o1 += redbuf[w * 3 + 1];
                    o2 += redbuf[w * 3 + 2];
                }
                const int oray = blockIdx.x * 2 + pass;
                out[oray * 3 + 0] = o0;
                out[oray * 3 + 1] = o1;
                out[oray * 3 + 2] = o2;
            }
        }
    }
}

extern "C" void kernel_launch(void* const* d_in, const int* in_sizes, int n_in,
                              void* d_out, int out_size)
{
    const float* rays_o    = (const float*)d_in[0];
    const float* rays_d    = (const float*)d_in[1];
    const float* dens      = (const float*)d_in[2];
    const float* k0g       = (const float*)d_in[3];
    const float* act_shift = (const float*)d_in[4];
    const float* w0        = (const float*)d_in[5];
    const float* b0        = (const float*)d_in[6];
    const float* w1        = (const float*)d_in[7];
    const float* b1        = (const float*)d_in[8];
    const float* w2        = (const float*)d_in[9];
    const float* b2        = (const float*)d_in[10];
    float* out = (float*)d_out;

    size_t smem = SMEM_FLOATS * sizeof(float);  // ~195 KB
    cudaFuncSetAttribute(mpi_render_kernel,
                         cudaFuncAttributeMaxDynamicSharedMemorySize, (int)smem);
    mpi_render_kernel<<<N_RAYS / 2, 256, smem>>>(
        rays_o, rays_d, dens, k0g, act_shift,
        w0, b0, w1, b1, w2, b2, out);
}